// round 13
// baseline (speedup 1.0000x reference)
#include <cuda_runtime.h>
#include <cstdint>

// ---------------- problem constants ----------------
#define D_IN   2048
#define D_H    512
#define BN_EPS 1e-3f

// ---------------- GEMM tiling ----------------
#define BM 128
#define BN 128
#define KC 128                      // k elems (s8) per chunk
#define NCHUNK (D_IN / KC)          // 16
#define BLK_BYTES 16384             // one 128x128 s8 pre-swizzled block
#define STAGE_BYTES (2 * BLK_BYTES) // A + B per stage = 32768
#define SMEM_DYN (3 * STAGE_BYTES)  // 98304 -> 2 CTAs/SM

// Blocked, pre-swizzled operand layouts:
//   g_Xq: [M/128][NCHUNK][16384]   block (bm, c)
//   g_Wq: [D_H/128][NCHUNK][16384] block (bn, c)
// In-block offset for (row 0..127, k 0..127):
//   row*128 + (((k>>4) ^ (row & 7)) << 4) + (k & 15)
__device__ __align__(16) signed char g_Xq[(size_t)32768 * D_IN];  // 64 MB
__device__ __align__(16) signed char g_Wq[(size_t)D_H * D_IN];    // 1 MB
__device__ float g_alpha[D_H];
__device__ float g_cbias[D_H];

// ---------------- PTX helpers ----------------
__device__ __forceinline__ uint32_t smem_u32(const void* p) {
    return (uint32_t)__cvta_generic_to_shared(p);
}
__device__ __forceinline__ void ldsm4(uint32_t* r, uint32_t addr) {
    asm volatile("ldmatrix.sync.aligned.m8n8.x4.shared.b16 {%0,%1,%2,%3}, [%4];"
                 : "=r"(r[0]), "=r"(r[1]), "=r"(r[2]), "=r"(r[3]) : "r"(addr));
}
__device__ __forceinline__ void mma_s8(int* c, const uint32_t* a,
                                       uint32_t b0, uint32_t b1) {
    asm volatile(
        "mma.sync.aligned.m16n8k32.row.col.s32.s8.s8.s32 "
        "{%0,%1,%2,%3}, {%4,%5,%6,%7}, {%8,%9}, {%0,%1,%2,%3};"
        : "+r"(c[0]), "+r"(c[1]), "+r"(c[2]), "+r"(c[3])
        : "r"(a[0]), "r"(a[1]), "r"(a[2]), "r"(a[3]), "r"(b0), "r"(b1));
}
__device__ __forceinline__ uint32_t prmt(uint32_t a, uint32_t b, uint32_t sel) {
    uint32_t d;
    asm("prmt.b32 %0, %1, %2, %3;" : "=r"(d) : "r"(a), "r"(b), "r"(sel));
    return d;
}
__device__ __forceinline__ uint32_t pk4(uint4 u) {
    uint32_t s01 = prmt(u.x, u.y, 0x00FBu);
    uint32_t s23 = prmt(u.z, u.w, 0x00FBu);
    return prmt(s01, s23, 0x5410u) | 0x01010101u;
}
// ---- bulk copy + mbarrier
__device__ __forceinline__ void bulk_g2s(uint32_t dst, const void* src,
                                         uint32_t bytes, uint32_t mbar) {
    asm volatile(
        "cp.async.bulk.shared::cta.global.mbarrier::complete_tx::bytes "
        "[%0], [%1], %2, [%3];"
        :: "r"(dst), "l"(src), "r"(bytes), "r"(mbar) : "memory");
}
__device__ __forceinline__ void mbar_init(uint32_t addr, uint32_t count) {
    asm volatile("mbarrier.init.shared.b64 [%0], %1;" :: "r"(addr), "r"(count) : "memory");
}
__device__ __forceinline__ void mbar_expect_tx(uint32_t addr, uint32_t tx) {
    asm volatile("mbarrier.arrive.expect_tx.shared.b64 _, [%0], %1;"
                 :: "r"(addr), "r"(tx) : "memory");
}
__device__ __forceinline__ void fence_proxy_async() {
    asm volatile("fence.proxy.async.shared::cta;" ::: "memory");
}
__device__ __forceinline__ void mbar_wait(uint32_t addr, uint32_t parity) {
    uint32_t done;
    asm volatile("{\n\t.reg .pred p;\n\t"
                 "mbarrier.try_wait.parity.acquire.cta.shared::cta.b64 p, [%1], %2;\n\t"
                 "selp.b32 %0, 1, 0, p;\n\t}"
                 : "=r"(done) : "r"(addr), "r"(parity) : "memory");
    while (!done) {
        asm volatile("{\n\t.reg .pred p;\n\t"
                     "mbarrier.try_wait.parity.acquire.cta.shared::cta.b64 p, [%1], %2, 0x989680;\n\t"
                     "selp.b32 %0, 1, 0, p;\n\t}"
                     : "=r"(done) : "r"(addr), "r"(parity) : "memory");
    }
}

// ---------------- prep: W transpose + sign + BN fold (blocked-swizzled out) --
__global__ __launch_bounds__(256)
void qdbn_prep_kernel(const float* __restrict__ W,
                      const float* __restrict__ b,
                      const float* __restrict__ beta,
                      const float* __restrict__ mean,
                      const float* __restrict__ var) {
    __shared__ signed char tile[32][33];
    const int n0 = blockIdx.x * 32;
    const int k0 = blockIdx.y * 32;
    const int tx = threadIdx.x;   // 32
    const int ty = threadIdx.y;   // 8

    #pragma unroll
    for (int i = 0; i < 32; i += 8) {
        float w = W[(size_t)(k0 + ty + i) * D_H + (n0 + tx)];
        tile[ty + i][tx] = (w >= 0.0f) ? 1 : -1;
    }
    __syncthreads();
    #pragma unroll
    for (int i = 0; i < 32; i += 8) {
        int n = n0 + ty + i;
        int k = k0 + tx;
        size_t blk = (size_t)((n >> 7) * NCHUNK + (k >> 7)) * BLK_BYTES;
        uint32_t off = (uint32_t)((n & 127) * 128)
                     + (uint32_t)(((((k >> 4) & 7) ^ (n & 7)) << 4) | (k & 15));
        g_Wq[blk + off] = tile[tx][ty + i];
    }

    if (blockIdx.x == 0 && blockIdx.y == 0) {
        int t = ty * 32 + tx;
        #pragma unroll
        for (int idx = t; idx < D_H; idx += 256) {
            float inv = rsqrtf(var[idx] + BN_EPS);
            g_alpha[idx] = inv;
            g_cbias[idx] = (b[idx] - mean[idx]) * inv + beta[idx];
        }
    }
}

// ---------------- pass 1: binarize X fp32 -> s8 blocked-swizzled ------------
__global__ __launch_bounds__(256)
void qdbn_binarize_kernel(const float* __restrict__ X) {
    const int blk = blockIdx.x;            // bm*NCHUNK + c
    const int bm  = blk / NCHUNK;
    const int c   = blk % NCHUNK;
    signed char* dst = g_Xq + (size_t)blk * BLK_BYTES;

    #pragma unroll
    for (int it = 0; it < 4; ++it) {
        int gid = it * 256 + threadIdx.x;  // 0..1023
        int row = gid >> 3;
        int g   = gid & 7;
        const uint4* src = (const uint4*)(X + (size_t)(bm * 128 + row) * D_IN
                                          + c * KC + g * 16);
        uint4 o;
        o.x = pk4(src[0]);
        o.y = pk4(src[1]);
        o.z = pk4(src[2]);
        o.w = pk4(src[3]);
        *(uint4*)(dst + row * 128 + ((g ^ (row & 7)) << 4)) = o;
    }
}

// ---------------- GEMM: s8 IMMA, operands via cp.async.bulk -----------------
// CTA 128(M) x 128(N), 128 threads = 4 warps as 2(M) x 2(N) -> warp 64x64.
// 2 CTAs/SM (96KB smem each); reg cap 65536/256 = 256/thread -> acc[128] fits
// with NO spills (R11's failure was 512 threads = 128-reg cap).
// Halves LDSM traffic vs 8-warp layout: A,B each read 2x (not 2x/4x).
__global__ __launch_bounds__(128, 2)
void qdbn_imma_kernel(float* __restrict__ out) {
    extern __shared__ char dyn_smem[];
    __shared__ __align__(8) unsigned long long s_mbar[3];
    const uint32_t base = smem_u32(dyn_smem);
    const uint32_t mb0  = smem_u32(&s_mbar[0]);

    const int tid  = threadIdx.x;
    const int wid  = tid >> 5;
    const int lane = tid & 31;
    const int m0 = blockIdx.y * BM;
    const int n0 = blockIdx.x * BN;
    const int wm = (wid >> 1) * 64;   // warp M offset (2 rows of warps)
    const int wn = (wid & 1) * 64;    // warp N offset (2 cols of warps)

    // ldmatrix per-lane addressing (mapping proven R9-R12)
    const int t8 = lane >> 3;
    const int rr = lane & 7;
    const uint32_t a_row_off = (uint32_t)(wm + (t8 & 1) * 8 + rr) * KC;
    const uint32_t a_kt = (uint32_t)(t8 >> 1);
    const uint32_t b_row_off = (uint32_t)(wn + (t8 >> 1) * 8 + rr) * KC;
    const uint32_t b_kt = (uint32_t)(t8 & 1);

    const signed char* Asrc = g_Xq + (size_t)blockIdx.y * NCHUNK * BLK_BYTES;
    const signed char* Bsrc = g_Wq + (size_t)blockIdx.x * NCHUNK * BLK_BYTES;

    if (tid == 0) {
        mbar_init(mb0 + 0, 1);
        mbar_init(mb0 + 8, 1);
        mbar_init(mb0 + 16, 1);
        fence_proxy_async();
    }
    __syncthreads();

    auto issue_chunk = [&](int c) {            // tid0 only
        const int s = c % 3;
        const uint32_t mb = mb0 + s * 8;
        const uint32_t as = base + s * STAGE_BYTES;
        mbar_expect_tx(mb, STAGE_BYTES);
        bulk_g2s(as,             Asrc + (size_t)c * BLK_BYTES, BLK_BYTES, mb);
        bulk_g2s(as + BLK_BYTES, Bsrc + (size_t)c * BLK_BYTES, BLK_BYTES, mb);
    };

    if (tid == 0) { issue_chunk(0); issue_chunk(1); issue_chunk(2); }

    int acc[4][8][4];
    #pragma unroll
    for (int mf = 0; mf < 4; ++mf)
        #pragma unroll
        for (int nf = 0; nf < 8; ++nf)
            #pragma unroll
            for (int q = 0; q < 4; ++q) acc[mf][nf][q] = 0;

    for (int c = 0; c < NCHUNK; ++c) {
        const int s = c % 3;
        mbar_wait(mb0 + s * 8, (uint32_t)((c / 3) & 1));

        const uint32_t a_s = base + s * STAGE_BYTES;
        const uint32_t b_s = a_s + BLK_BYTES;

        #pragma unroll
        for (int ks = 0; ks < 4; ++ks) {
            uint32_t a[4][4];
            const uint32_t ga = (uint32_t)(2 * ks) + a_kt;
            #pragma unroll
            for (int mf = 0; mf < 4; ++mf)
                ldsm4(a[mf], a_s + a_row_off + mf * 16 * KC + ((ga ^ rr) << 4));
            const uint32_t gb = (uint32_t)(2 * ks) + b_kt;
            #pragma unroll
            for (int np = 0; np < 4; ++np) {
                uint32_t bb[4];
                ldsm4(bb, b_s + b_row_off + np * 16 * KC + ((gb ^ rr) << 4));
                #pragma unroll
                for (int mf = 0; mf < 4; ++mf) {
                    mma_s8(acc[mf][2 * np],     a[mf], bb[0], bb[1]);
                    mma_s8(acc[mf][2 * np + 1], a[mf], bb[2], bb[3]);
                }
            }
        }

        __syncthreads();                       // all reads of stage s done
        if (tid == 0 && c + 3 < NCHUNK) issue_chunk(c + 3);  // reuses stage s
    }

    // ---- epilogue: BN fold + fp32 store
    const int lr = lane >> 2;
    const int lc = (lane & 3) * 2;
    #pragma unroll
    for (int nf = 0; nf < 8; ++nf) {
        const int cn = n0 + wn + nf * 8 + lc;
        const float al0 = g_alpha[cn],     cb0 = g_cbias[cn];
        const float al1 = g_alpha[cn + 1], cb1 = g_cbias[cn + 1];
        #pragma unroll
        for (int mf = 0; mf < 4; ++mf) {
            const int r0 = m0 + wm + mf * 16 + lr;
            float2 v0, v1;
            v0.x = (float)acc[mf][nf][0] * al0 + cb0;
            v0.y = (float)acc[mf][nf][1] * al1 + cb1;
            v1.x = (float)acc[mf][nf][2] * al0 + cb0;
            v1.y = (float)acc[mf][nf][3] * al1 + cb1;
            *(float2*)(out + (size_t)r0 * D_H + cn) = v0;
            *(float2*)(out + (size_t)(r0 + 8) * D_H + cn) = v1;
        }
    }
}

// ---------------- launch ----------------
extern "C" void kernel_launch(void* const* d_in, const int* in_sizes, int n_in,
                              void* d_out, int out_size) {
    const float* X    = (const float*)d_in[0];
    const float* W    = (const float*)d_in[1];
    const float* b    = (const float*)d_in[2];
    const float* beta = (const float*)d_in[3];
    const float* mean = (const float*)d_in[4];
    const float* var  = (const float*)d_in[5];
    float* out = (float*)d_out;

    const int M = in_sizes[0] / D_IN;   // 32768

    dim3 pb(32, 8);
    dim3 pg(D_H / 32, D_IN / 32);
    qdbn_prep_kernel<<<pg, pb>>>(W, b, beta, mean, var);

    qdbn_binarize_kernel<<<(M / 128) * NCHUNK, 256>>>(X);

    cudaFuncSetAttribute(qdbn_imma_kernel,
                         cudaFuncAttributeMaxDynamicSharedMemorySize, SMEM_DYN);
    dim3 grid(D_H / BN, M / BM);        // (4, 256) = 1024 CTAs
    qdbn_imma_kernel<<<grid, 128, SMEM_DYN>>>(out);
}

// round 14
// speedup vs baseline: 1.0848x; 1.0848x over previous
#include <cuda_runtime.h>
#include <cstdint>

// ---------------- problem constants ----------------
#define D_IN   2048
#define D_H    512
#define BN_EPS 1e-3f

// ---------------- GEMM tiling ----------------
#define BM 128
#define BN 128
#define KC 128                      // k elems (s8) per chunk
#define NCHUNK (D_IN / KC)          // 16
#define BLK_BYTES 16384             // one 128x128 s8 pre-swizzled block
#define STAGE_BYTES (2 * BLK_BYTES) // A + B per stage = 32768
#define SMEM_DYN (3 * STAGE_BYTES)  // 98304 -> 2 CTAs/SM

// Blocked, pre-swizzled operand layouts:
//   g_Xq: [M/128][NCHUNK][16384]   block (bm, c)
//   g_Wq: [D_H/128][NCHUNK][16384] block (bn, c)
// In-block offset for (row 0..127, k 0..127):
//   row*128 + (((k>>4) ^ (row & 7)) << 4) + (k & 15)
__device__ __align__(16) signed char g_Xq[(size_t)32768 * D_IN];  // 64 MB
__device__ __align__(16) signed char g_Wq[(size_t)D_H * D_IN];    // 1 MB
__device__ float g_alpha[D_H];
__device__ float g_cbias[D_H];

// ---------------- PTX helpers ----------------
__device__ __forceinline__ uint32_t smem_u32(const void* p) {
    return (uint32_t)__cvta_generic_to_shared(p);
}
__device__ __forceinline__ void ldsm4(uint32_t* r, uint32_t addr) {
    asm volatile("ldmatrix.sync.aligned.m8n8.x4.shared.b16 {%0,%1,%2,%3}, [%4];"
                 : "=r"(r[0]), "=r"(r[1]), "=r"(r[2]), "=r"(r[3]) : "r"(addr));
}
__device__ __forceinline__ void mma_s8(int* c, const uint32_t* a,
                                       uint32_t b0, uint32_t b1) {
    asm volatile(
        "mma.sync.aligned.m16n8k32.row.col.s32.s8.s8.s32 "
        "{%0,%1,%2,%3}, {%4,%5,%6,%7}, {%8,%9}, {%0,%1,%2,%3};"
        : "+r"(c[0]), "+r"(c[1]), "+r"(c[2]), "+r"(c[3])
        : "r"(a[0]), "r"(a[1]), "r"(a[2]), "r"(a[3]), "r"(b0), "r"(b1));
}
__device__ __forceinline__ uint32_t prmt(uint32_t a, uint32_t b, uint32_t sel) {
    uint32_t d;
    asm("prmt.b32 %0, %1, %2, %3;" : "=r"(d) : "r"(a), "r"(b), "r"(sel));
    return d;
}
__device__ __forceinline__ uint32_t pk4(uint4 u) {
    uint32_t s01 = prmt(u.x, u.y, 0x00FBu);
    uint32_t s23 = prmt(u.z, u.w, 0x00FBu);
    return prmt(s01, s23, 0x5410u) | 0x01010101u;
}
// ---- bulk copy + mbarrier
__device__ __forceinline__ void bulk_g2s(uint32_t dst, const void* src,
                                         uint32_t bytes, uint32_t mbar) {
    asm volatile(
        "cp.async.bulk.shared::cta.global.mbarrier::complete_tx::bytes "
        "[%0], [%1], %2, [%3];"
        :: "r"(dst), "l"(src), "r"(bytes), "r"(mbar) : "memory");
}
__device__ __forceinline__ void mbar_init(uint32_t addr, uint32_t count) {
    asm volatile("mbarrier.init.shared.b64 [%0], %1;" :: "r"(addr), "r"(count) : "memory");
}
__device__ __forceinline__ void mbar_expect_tx(uint32_t addr, uint32_t tx) {
    asm volatile("mbarrier.arrive.expect_tx.shared.b64 _, [%0], %1;"
                 :: "r"(addr), "r"(tx) : "memory");
}
__device__ __forceinline__ void mbar_arrive(uint32_t addr) {
    asm volatile("mbarrier.arrive.shared.b64 _, [%0];" :: "r"(addr) : "memory");
}
__device__ __forceinline__ void fence_proxy_async() {
    asm volatile("fence.proxy.async.shared::cta;" ::: "memory");
}
__device__ __forceinline__ void mbar_wait(uint32_t addr, uint32_t parity) {
    uint32_t done;
    asm volatile("{\n\t.reg .pred p;\n\t"
                 "mbarrier.try_wait.parity.acquire.cta.shared::cta.b64 p, [%1], %2;\n\t"
                 "selp.b32 %0, 1, 0, p;\n\t}"
                 : "=r"(done) : "r"(addr), "r"(parity) : "memory");
    while (!done) {
        asm volatile("{\n\t.reg .pred p;\n\t"
                     "mbarrier.try_wait.parity.acquire.cta.shared::cta.b64 p, [%1], %2, 0x989680;\n\t"
                     "selp.b32 %0, 1, 0, p;\n\t}"
                     : "=r"(done) : "r"(addr), "r"(parity) : "memory");
    }
}

// ---------------- prep: W transpose + sign + BN fold (blocked-swizzled out) --
__global__ __launch_bounds__(256)
void qdbn_prep_kernel(const float* __restrict__ W,
                      const float* __restrict__ b,
                      const float* __restrict__ beta,
                      const float* __restrict__ mean,
                      const float* __restrict__ var) {
    __shared__ signed char tile[32][33];
    const int n0 = blockIdx.x * 32;
    const int k0 = blockIdx.y * 32;
    const int tx = threadIdx.x;   // 32
    const int ty = threadIdx.y;   // 8

    #pragma unroll
    for (int i = 0; i < 32; i += 8) {
        float w = W[(size_t)(k0 + ty + i) * D_H + (n0 + tx)];
        tile[ty + i][tx] = (w >= 0.0f) ? 1 : -1;
    }
    __syncthreads();
    #pragma unroll
    for (int i = 0; i < 32; i += 8) {
        int n = n0 + ty + i;
        int k = k0 + tx;
        size_t blk = (size_t)((n >> 7) * NCHUNK + (k >> 7)) * BLK_BYTES;
        uint32_t off = (uint32_t)((n & 127) * 128)
                     + (uint32_t)(((((k >> 4) & 7) ^ (n & 7)) << 4) | (k & 15));
        g_Wq[blk + off] = tile[tx][ty + i];
    }

    if (blockIdx.x == 0 && blockIdx.y == 0) {
        int t = ty * 32 + tx;
        #pragma unroll
        for (int idx = t; idx < D_H; idx += 256) {
            float inv = rsqrtf(var[idx] + BN_EPS);
            g_alpha[idx] = inv;
            g_cbias[idx] = (b[idx] - mean[idx]) * inv + beta[idx];
        }
    }
}

// ---------------- pass 1: binarize X fp32 -> s8 blocked-swizzled ------------
__global__ __launch_bounds__(256)
void qdbn_binarize_kernel(const float* __restrict__ X) {
    const int blk = blockIdx.x;            // bm*NCHUNK + c
    const int bm  = blk / NCHUNK;
    const int c   = blk % NCHUNK;
    signed char* dst = g_Xq + (size_t)blk * BLK_BYTES;

    #pragma unroll
    for (int it = 0; it < 4; ++it) {
        int gid = it * 256 + threadIdx.x;  // 0..1023
        int row = gid >> 3;
        int g   = gid & 7;
        const uint4* src = (const uint4*)(X + (size_t)(bm * 128 + row) * D_IN
                                          + c * KC + g * 16);
        uint4 o;
        o.x = pk4(src[0]);
        o.y = pk4(src[1]);
        o.z = pk4(src[2]);
        o.w = pk4(src[3]);
        *(uint4*)(dst + row * 128 + ((g ^ (row & 7)) << 4)) = o;
    }
}

// ---------------- GEMM: s8 IMMA, bulk-TMA full/empty pipeline ---------------
// CTA 128(M) x 128(N), 256 threads = 8 warps as 4(M) x 2(N) -> warp 32x64.
// 2 CTAs/SM (96KB). Full/empty mbarrier pairs replace per-chunk __syncthreads:
// consumers arrive empty[s] (count=8, elected lane per warp, right after the
// chunk's last LDSM); only tid0 waits empty before reissue. Warps drift freely.
__global__ __launch_bounds__(256, 2)
void qdbn_imma_kernel(float* __restrict__ out) {
    extern __shared__ char dyn_smem[];
    __shared__ __align__(8) unsigned long long s_mbar[6];   // fb[0..2], eb[0..2]
    const uint32_t base = smem_u32(dyn_smem);
    const uint32_t fb0  = smem_u32(&s_mbar[0]);
    const uint32_t eb0  = smem_u32(&s_mbar[3]);

    const int tid  = threadIdx.x;
    const int wid  = tid >> 5;
    const int lane = tid & 31;
    const int m0 = blockIdx.y * BM;
    const int n0 = blockIdx.x * BN;
    const int wm = (wid >> 1) * 32;   // warp M offset
    const int wn = (wid & 1) * 64;    // warp N offset

    // ldmatrix per-lane addressing (mapping proven R9-R13)
    const int t8 = lane >> 3;
    const int rr = lane & 7;
    const uint32_t a_row_off = (uint32_t)(wm + (t8 & 1) * 8 + rr) * KC;
    const uint32_t a_kt = (uint32_t)(t8 >> 1);
    const uint32_t b_row_off = (uint32_t)(wn + (t8 >> 1) * 8 + rr) * KC;
    const uint32_t b_kt = (uint32_t)(t8 & 1);

    const signed char* Asrc = g_Xq + (size_t)blockIdx.y * NCHUNK * BLK_BYTES;
    const signed char* Bsrc = g_Wq + (size_t)blockIdx.x * NCHUNK * BLK_BYTES;

    if (tid == 0) {
        #pragma unroll
        for (int s = 0; s < 3; ++s) {
            mbar_init(fb0 + s * 8, 1);    // tx-based completion
            mbar_init(eb0 + s * 8, 8);    // one arrive per warp
        }
        fence_proxy_async();
    }
    __syncthreads();

    auto issue_chunk = [&](int c) {            // tid0 only
        const int s = c % 3;
        const uint32_t mb = fb0 + s * 8;
        const uint32_t as = base + s * STAGE_BYTES;
        mbar_expect_tx(mb, STAGE_BYTES);
        bulk_g2s(as,             Asrc + (size_t)c * BLK_BYTES, BLK_BYTES, mb);
        bulk_g2s(as + BLK_BYTES, Bsrc + (size_t)c * BLK_BYTES, BLK_BYTES, mb);
    };

    if (tid == 0) { issue_chunk(0); issue_chunk(1); issue_chunk(2); }

    int acc[2][8][4];
    #pragma unroll
    for (int mf = 0; mf < 2; ++mf)
        #pragma unroll
        for (int nf = 0; nf < 8; ++nf)
            #pragma unroll
            for (int q = 0; q < 4; ++q) acc[mf][nf][q] = 0;

    for (int c = 0; c < NCHUNK; ++c) {
        const int s = c % 3;
        const uint32_t par = (uint32_t)((c / 3) & 1);
        mbar_wait(fb0 + s * 8, par);

        const uint32_t a_s = base + s * STAGE_BYTES;
        const uint32_t b_s = a_s + BLK_BYTES;

        #pragma unroll
        for (int ks = 0; ks < 4; ++ks) {
            uint32_t a[2][4], bb[4][4];
            const uint32_t ga = (uint32_t)(2 * ks) + a_kt;
            #pragma unroll
            for (int mf = 0; mf < 2; ++mf)
                ldsm4(a[mf], a_s + a_row_off + mf * 16 * KC + ((ga ^ rr) << 4));
            const uint32_t gb = (uint32_t)(2 * ks) + b_kt;
            #pragma unroll
            for (int np = 0; np < 4; ++np)
                ldsm4(bb[np], b_s + b_row_off + np * 16 * KC + ((gb ^ rr) << 4));

            if (ks == 3) {                 // all smem reads of stage s done
                __syncwarp();
                if (lane == 0) mbar_arrive(eb0 + s * 8);
            }
            #pragma unroll
            for (int np = 0; np < 4; ++np)
                #pragma unroll
                for (int mf = 0; mf < 2; ++mf) {
                    mma_s8(acc[mf][2 * np],     a[mf], bb[np][0], bb[np][1]);
                    mma_s8(acc[mf][2 * np + 1], a[mf], bb[np][2], bb[np][3]);
                }
        }

        // producer: reuse stage s for chunk c+3 once all 8 warps arrived
        if (tid == 0 && c + 3 < NCHUNK) {
            mbar_wait(eb0 + s * 8, par);
            issue_chunk(c + 3);
        }
    }

    // ---- epilogue: BN fold + fp32 store
    const int lr = lane >> 2;
    const int lc = (lane & 3) * 2;
    #pragma unroll
    for (int nf = 0; nf < 8; ++nf) {
        const int cn = n0 + wn + nf * 8 + lc;
        const float al0 = g_alpha[cn],     cb0 = g_cbias[cn];
        const float al1 = g_alpha[cn + 1], cb1 = g_cbias[cn + 1];
        #pragma unroll
        for (int mf = 0; mf < 2; ++mf) {
            const int r0 = m0 + wm + mf * 16 + lr;
            float2 v0, v1;
            v0.x = (float)acc[mf][nf][0] * al0 + cb0;
            v0.y = (float)acc[mf][nf][1] * al1 + cb1;
            v1.x = (float)acc[mf][nf][2] * al0 + cb0;
            v1.y = (float)acc[mf][nf][3] * al1 + cb1;
            *(float2*)(out + (size_t)r0 * D_H + cn) = v0;
            *(float2*)(out + (size_t)(r0 + 8) * D_H + cn) = v1;
        }
    }
}

// ---------------- launch ----------------
extern "C" void kernel_launch(void* const* d_in, const int* in_sizes, int n_in,
                              void* d_out, int out_size) {
    const float* X    = (const float*)d_in[0];
    const float* W    = (const float*)d_in[1];
    const float* b    = (const float*)d_in[2];
    const float* beta = (const float*)d_in[3];
    const float* mean = (const float*)d_in[4];
    const float* var  = (const float*)d_in[5];
    float* out = (float*)d_out;

    const int M = in_sizes[0] / D_IN;   // 32768

    dim3 pb(32, 8);
    dim3 pg(D_H / 32, D_IN / 32);
    qdbn_prep_kernel<<<pg, pb>>>(W, b, beta, mean, var);

    qdbn_binarize_kernel<<<(M / 128) * NCHUNK, 256>>>(X);

    cudaFuncSetAttribute(qdbn_imma_kernel,
                         cudaFuncAttributeMaxDynamicSharedMemorySize, SMEM_DYN);
    dim3 grid(D_H / BN, M / BM);        // (4, 256) = 1024 CTAs
    qdbn_imma_kernel<<<grid, 256, SMEM_DYN>>>(out);
}